// round 14
// baseline (speedup 1.0000x reference)
#include <cuda_runtime.h>
#include <math.h>
#include <stdint.h>

#define B_  64
#define S_  64
#define F_  2048
#define H_  512
#define G4_ 2048
#define P_  20
#define R_  4096   // B*S

// ---------------- scratch (static device globals; no allocs) ----------------
__device__ float g_fuse[R_ * H_];        // [B*S, H]   8 MB
__device__ float g_xg[S_ * B_ * G4_];    // [S][B][4H] 32 MB
__device__ float g_hT[2][H_ * B_];       // hidden state, TRANSPOSED [k][batch]
__device__ float g_ddp[B_ * S_];         // per-(b,s) prototype partial
__device__ int   g_cat[B_];              // normalized category
__device__ unsigned g_bar_count = 0u;    // monotonic ticket counter (never reset)

__device__ __forceinline__ float sigmoidf_(float x) { return 1.0f / (1.0f + expf(-x)); }

__device__ __forceinline__ float tanh_fast(float x) {
    float r;
    asm("tanh.approx.f32 %0, %1;" : "=f"(r) : "f"(x));
    return r;
}
__device__ __forceinline__ float sig_fast(float x) {
    return fmaf(tanh_fast(0.5f * x), 0.5f, 0.5f);
}

// Ticket barrier with release-fence + acquire-poll.
__device__ __forceinline__ void grid_bar_arrive_wait() {
    __threadfence();   // release h stores
    unsigned ticket = atomicAdd(&g_bar_count, 1u);
    unsigned target = (ticket & ~127u) + 128u;
    for (;;) {
        unsigned cur;
        asm volatile("ld.acquire.gpu.u32 %0, [%1];"
                     : "=r"(cur) : "l"(&g_bar_count) : "memory");
        if (cur >= target) break;
        __nanosleep(20);
    }
}

__device__ __forceinline__ unsigned f2tf32(float x) {
    unsigned u;
    asm("cvt.rna.tf32.f32 %0, %1;" : "=r"(u) : "f"(x));
    return u;
}

// ---------------- category dtype normalization (int64 vs int32) -------------
__global__ void cat_normalize(const int* __restrict__ w) {
    if (threadIdx.x == 0 && blockIdx.x == 0) {
        bool oddzero = true, evenok = true;
        for (int i = 0; i < 32; i++) {
            int lo = w[2 * i], hi = w[2 * i + 1];
            if (hi != 0) oddzero = false;
            if (lo < 0 || lo > 2) evenok = false;
        }
        if (oddzero && evenok) {
            const long long* c = (const long long*)w;
            for (int b = 0; b < B_; b++) g_cat[b] = (int)c[b];
        } else {
            for (int b = 0; b < B_; b++) g_cat[b] = w[b];
        }
    }
}

// ---------------- proto rows, 256-thread device function --------------------
// Computes g_ddp[r] for one (b,s) row: sum_p W_dd[s*P+p] * log((d+1)/(d+1e-8)).
__device__ void proto_rows_256(int r0, int stride, int count,
                               const float* __restrict__ v,
                               const float* __restrict__ proto,
                               const float* __restrict__ W_dd,
                               float* sm)
{
    float* wsum = sm;            // [8][P_]
    float* psum = sm + 8 * P_;   // [P_]
    const int tid = threadIdx.x, wid = tid >> 5, lane = tid & 31;

    for (int j = 0; j < count; j++) {
        int r = r0 + j * stride;
        const int s = r & 63;
        const float4* vrow = reinterpret_cast<const float4*>(&v[(size_t)r * F_]);

        float acc[P_];
        #pragma unroll
        for (int p = 0; p < P_; p++) acc[p] = 0.0f;

        #pragma unroll
        for (int i = 0; i < 2; i++) {
            int f4 = tid + i * 256;
            float4 vv = __ldg(&vrow[f4]);
            #pragma unroll
            for (int p = 0; p < P_; p++) {
                float4 pv = __ldg(reinterpret_cast<const float4*>(
                    &proto[(size_t)p * F_ + f4 * 4]));
                float d;
                d = vv.x - pv.x; acc[p] = fmaf(d, d, acc[p]);
                d = vv.y - pv.y; acc[p] = fmaf(d, d, acc[p]);
                d = vv.z - pv.z; acc[p] = fmaf(d, d, acc[p]);
                d = vv.w - pv.w; acc[p] = fmaf(d, d, acc[p]);
            }
        }
        #pragma unroll
        for (int p = 0; p < P_; p++) {
            float x = acc[p];
            #pragma unroll
            for (int o = 16; o > 0; o >>= 1) x += __shfl_down_sync(0xffffffffu, x, o);
            acc[p] = x;
        }
        if (lane == 0)
            for (int p = 0; p < P_; p++) wsum[wid * P_ + p] = acc[p];
        __syncthreads();
        if (tid < P_) {
            float d = 0.0f;
            #pragma unroll
            for (int ww = 0; ww < 8; ww++) d += wsum[ww * P_ + tid];
            float df = logf((d + 1.0f) / (d + 1e-8f));
            psum[tid] = df * W_dd[s * P_ + tid];
        }
        __syncthreads();
        if (tid == 0) {
            float t = 0.0f;
            for (int p = 0; p < P_; p++) t += psum[p];
            g_ddp[r] = t;
        }
        __syncthreads();
    }
}

// =================== tf32 tensor-core GEMM (both big GEMMs) ==================
#define TBM 128
#define TBN 64
#define TBK 32
#define AS_FLOATS 4096
#define BUF_FLOATS 6144
#define FUSE_TILES 256     // (512/64) x (4096/128)
#define XG_TILES   1024    // (2048/64) x (4096/128)
#define PROTO_BLK  256

template<int KDIM, int NDIM>
__device__ __forceinline__ void tf32_mainloop(
    const float* __restrict__ A, const float* __restrict__ W,
    float* sm, int brow, int bcol, float (&acc)[8][4])
{
    const int tid  = threadIdx.x;
    const int lane = tid & 31;
    const int wid  = tid >> 5;
    const int wm   = wid >> 1;
    const int wn   = wid & 1;

    #pragma unroll
    for (int i = 0; i < 8; i++)
        #pragma unroll
        for (int j = 0; j < 4; j++) acc[i][j] = 0.0f;

    float4 a_ld[4], b_ld[2];

    auto load_g = [&](int kt) {
        #pragma unroll
        for (int j = 0; j < 4; j++) {
            int r = (tid >> 3) + j * 32;
            a_ld[j] = *reinterpret_cast<const float4*>(
                &A[(size_t)(brow + r) * KDIM + kt * TBK + (tid & 7) * 4]);
        }
        #pragma unroll
        for (int j = 0; j < 2; j++) {
            int f = tid + j * 256;
            int kr = f >> 4, c4 = (f & 15) * 4;
            b_ld[j] = *reinterpret_cast<const float4*>(
                &W[(size_t)(kt * TBK + kr) * NDIM + bcol + c4]);
        }
    };

    auto sts = [&](float* buf) {
        #pragma unroll
        for (int j = 0; j < 4; j++) {
            int r = (tid >> 3) + j * 32;
            int c = (tid & 7) * 4;
            int mtile = r >> 4, rr = r & 15;
            int k8 = c >> 3;
            int sbase = (rr >> 3) + 2 * ((c >> 2) & 1);
            int lbase = (rr & 7) * 4;
            float* dst = buf + ((k8 * 8 + mtile) * 32) * 4 + sbase;
            const float* src = (const float*)&a_ld[j];
            #pragma unroll
            for (int i = 0; i < 4; i++)
                dst[(lbase + (i ^ k8)) * 4] = __uint_as_float(f2tf32(src[i]));
        }
        #pragma unroll
        for (int j = 0; j < 2; j++) {
            int f = tid + j * 256;
            int kr = f >> 4, c4 = (f & 15) * 4;
            int k8 = kr >> 3, kk = kr & 7;
            int slot = kk >> 2, lrow = kk & 3;
            const float* src = (const float*)&b_ld[j];
            #pragma unroll
            for (int i = 0; i < 4; i++) {
                int c = c4 + i;
                int ntile = c >> 3, cc = c & 7;
                int fsw = (cc * 4 + lrow) ^ (2 * ntile);
                buf[AS_FLOATS + ((k8 * 8 + ntile) * 32 + fsw) * 2 + slot] =
                    __uint_as_float(f2tf32(src[i]));
            }
        }
    };

    auto compute = [&](const float* buf) {
        #pragma unroll
        for (int k8 = 0; k8 < 4; k8++) {
            uint4 af[2];
            uint2 bf[4];
            #pragma unroll
            for (int mi = 0; mi < 2; mi++)
                af[mi] = *reinterpret_cast<const uint4*>(
                    buf + ((k8 * 8 + wm * 2 + mi) * 32 + (lane ^ k8)) * 4);
            #pragma unroll
            for (int ni = 0; ni < 4; ni++) {
                int nt = wn * 4 + ni;
                bf[ni] = *reinterpret_cast<const uint2*>(
                    buf + AS_FLOATS + ((k8 * 8 + nt) * 32 + (lane ^ (2 * nt))) * 2);
            }
            #pragma unroll
            for (int mi = 0; mi < 2; mi++)
                #pragma unroll
                for (int ni = 0; ni < 4; ni++) {
                    float* c = acc[mi * 4 + ni];
                    asm volatile(
                        "mma.sync.aligned.m16n8k8.row.col.f32.tf32.tf32.f32 "
                        "{%0,%1,%2,%3}, {%4,%5,%6,%7}, {%8,%9}, {%0,%1,%2,%3};"
                        : "+f"(c[0]), "+f"(c[1]), "+f"(c[2]), "+f"(c[3])
                        : "r"(af[mi].x), "r"(af[mi].y), "r"(af[mi].z), "r"(af[mi].w),
                          "r"(bf[ni].x), "r"(bf[ni].y));
                }
        }
    };

    constexpr int NIT = KDIM / TBK;
    load_g(0);
    sts(sm);
    __syncthreads();
    for (int kt = 0; kt < NIT; kt++) {
        const float* cur = sm + (size_t)(kt & 1) * BUF_FLOATS;
        float* nxt = sm + (size_t)((kt + 1) & 1) * BUF_FLOATS;
        if (kt + 1 < NIT) load_g(kt + 1);
        compute(cur);
        if (kt + 1 < NIT) sts(nxt);
        __syncthreads();
    }
}

// fuse = relu(v @ W_enc + b_enc) + cat_emb[cat]; extra blocks do proto rows 0..2047
__global__ __launch_bounds__(256) void fuse_tc(
    const float* __restrict__ A, const float* __restrict__ W,
    const float* __restrict__ bias, const float* __restrict__ cat_emb,
    const float* __restrict__ proto, const float* __restrict__ W_dd)
{
    extern __shared__ float sm[];
    if (blockIdx.x >= FUSE_TILES) {
        int pid = blockIdx.x - FUSE_TILES;
        proto_rows_256(pid, PROTO_BLK, 8, A, proto, W_dd, sm);  // rows 0..2047
        return;
    }
    const int bcol = (blockIdx.x & 7) * TBN;
    const int brow = (blockIdx.x >> 3) * TBM;
    float acc[8][4];
    tf32_mainloop<F_, H_>(A, W, sm, brow, bcol, acc);

    const int tid = threadIdx.x, lane = tid & 31, wid = tid >> 5;
    const int wm = wid >> 1, wn = wid & 1;
    #pragma unroll
    for (int mi = 0; mi < 2; mi++)
        #pragma unroll
        for (int ni = 0; ni < 4; ni++) {
            const float* c = acc[mi * 4 + ni];
            int row0 = brow + wm * 32 + mi * 16 + (lane >> 2);
            int col0 = bcol + wn * 32 + ni * 8 + (lane & 3) * 2;
            #pragma unroll
            for (int q = 0; q < 4; q++) {
                int row = row0 + (q >> 1) * 8;
                int col = col0 + (q & 1);
                int b = row >> 6;
                float val = fmaxf(c[q] + bias[col], 0.0f) + cat_emb[g_cat[b] * H_ + col];
                g_fuse[(size_t)row * H_ + col] = val;
            }
        }
}

// x_gates = fuse @ Wx + (bx+bh); extra blocks do proto rows 2048..4095
__global__ __launch_bounds__(256) void xg_tc(
    const float* __restrict__ W, const float* __restrict__ bx,
    const float* __restrict__ bh,
    const float* __restrict__ v, const float* __restrict__ proto,
    const float* __restrict__ W_dd)
{
    extern __shared__ float sm[];
    if (blockIdx.x >= XG_TILES) {
        int pid = blockIdx.x - XG_TILES;
        proto_rows_256(2048 + pid, PROTO_BLK, 8, v, proto, W_dd, sm);
        return;
    }
    const int bcol = (blockIdx.x & 31) * TBN;
    const int brow = (blockIdx.x >> 5) * TBM;
    float acc[8][4];
    tf32_mainloop<H_, G4_>(g_fuse, W, sm, brow, bcol, acc);

    const int tid = threadIdx.x, lane = tid & 31, wid = tid >> 5;
    const int wm = wid >> 1, wn = wid & 1;
    #pragma unroll
    for (int mi = 0; mi < 2; mi++)
        #pragma unroll
        for (int ni = 0; ni < 4; ni++) {
            const float* c = acc[mi * 4 + ni];
            int row0 = brow + wm * 32 + mi * 16 + (lane >> 2);
            int col0 = bcol + wn * 32 + ni * 8 + (lane & 3) * 2;
            #pragma unroll
            for (int q = 0; q < 4; q++) {
                int row = row0 + (q >> 1) * 8;
                int col = col0 + (q & 1);
                int bb = row >> 6, ss = row & 63;
                g_xg[(size_t)(ss * B_ + bb) * G4_ + col] = c[q] + bx[col] + bh[col];
            }
        }
}

// ---------------- persistent LSTM: tensor-core recurrent GEMM ----------------
__global__ __launch_bounds__(256) void lstm_persist(const float* __restrict__ Wh)
{
    extern __shared__ float sm[];
    float* whsf = sm;                  // 32 KB
    float* as_  = sm + 8192;           // 128 KB
    float* gs_  = as_ + 32768;         // 34 KB
    float* cs_  = gs_ + 8 * 64 * 17;   // 1 KB

    const int tid   = threadIdx.x;
    const int jbase = blockIdx.x * 4;
    const int w = tid >> 5;
    const int l = tid & 31;

    const int cm  = tid >> 2;
    const int cjl = tid & 3;

    for (int idx = tid; idx < 8192; idx += 256) {
        int word = idx & 1, ll = (idx >> 1) & 31, nt = (idx >> 6) & 1, k8 = idx >> 7;
        int kk = (ll & 3) + word * 4, n = ll >> 2;
        int k = k8 * 8 + kk, c = nt * 8 + n;
        float v = Wh[(size_t)k * G4_ + (c >> 2) * H_ + jbase + (c & 3)];
        whsf[idx] = __uint_as_float(f2tf32(v));
    }
    cs_[tid] = 0.0f;
    __syncthreads();

    for (int s = 0; s < S_; s++) {
        const float* __restrict__ hT_in = g_hT[s & 1];
        float* __restrict__ hT_out      = g_hT[(s + 1) & 1];
        const float* __restrict__ xg_s  = &g_xg[(size_t)s * B_ * G4_];

        float xgp[4];
        #pragma unroll
        for (int g = 0; g < 4; g++)
            xgp[g] = __ldg(&xg_s[(size_t)cm * G4_ + g * H_ + jbase + cjl]);

        float acc[4][2][4];
        #pragma unroll
        for (int mt = 0; mt < 4; mt++)
            #pragma unroll
            for (int nt = 0; nt < 2; nt++)
                #pragma unroll
                for (int q = 0; q < 4; q++) acc[mt][nt][q] = 0.0f;

        if (s > 0) {
            const float4* src = reinterpret_cast<const float4*>(hT_in) + w * 1024;
            #pragma unroll
            for (int i = 0; i < 32; i++) {
                int f = l + i * 32;
                float4 v = __ldcg(&src[f]);
                int k  = w * 64 + (f >> 4);
                int m0 = (f & 15) * 4;
                float4 t;
                t.x = __uint_as_float(f2tf32(v.x));
                t.y = __uint_as_float(f2tf32(v.y));
                t.z = __uint_as_float(f2tf32(v.z));
                t.w = __uint_as_float(f2tf32(v.w));
                *reinterpret_cast<float4*>(&as_[k * 64 + (m0 ^ ((k & 3) * 8))]) = t;
            }
            __syncwarp();

            const int c0 = l & 3;
            const int sw = c0 * 8;
            const int r0 = l >> 2;
            #pragma unroll
            for (int k8l = 0; k8l < 8; k8l++) {
                int k8 = w * 8 + k8l;
                int k0 = k8 * 8 + c0;
                int k1 = k0 + 4;
                uint2 bf[2];
                #pragma unroll
                for (int nt = 0; nt < 2; nt++)
                    bf[nt] = *reinterpret_cast<const uint2*>(
                        &whsf[((k8 * 2 + nt) * 32 + l) * 2]);
                #pragma unroll
                for (int mt = 0; mt < 4; mt++) {
                    int r = mt * 16 + r0;
                    unsigned a0 = __float_as_uint(as_[k0 * 64 + (r ^ sw)]);
                    unsigned a1 = __float_as_uint(as_[k0 * 64 + ((r + 8) ^ sw)]);
                    unsigned a2 = __float_as_uint(as_[k1 * 64 + (r ^ sw)]);
                    unsigned a3 = __float_as_uint(as_[k1 * 64 + ((r + 8) ^ sw)]);
                    #pragma unroll
                    for (int nt = 0; nt < 2; nt++) {
                        float* c = acc[mt][nt];
                        asm volatile(
                            "mma.sync.aligned.m16n8k8.row.col.f32.tf32.tf32.f32 "
                            "{%0,%1,%2,%3}, {%4,%5,%6,%7}, {%8,%9}, {%0,%1,%2,%3};"
                            : "+f"(c[0]), "+f"(c[1]), "+f"(c[2]), "+f"(c[3])
                            : "r"(a0), "r"(a1), "r"(a2), "r"(a3),
                              "r"(bf[nt].x), "r"(bf[nt].y));
                    }
                }
            }
        }

        {
            float* gq = gs_ + w * (64 * 17);
            #pragma unroll
            for (int mt = 0; mt < 4; mt++)
                #pragma unroll
                for (int nt = 0; nt < 2; nt++)
                    #pragma unroll
                    for (int q = 0; q < 4; q++) {
                        int row = mt * 16 + (l >> 2) + (q >> 1) * 8;
                        int col = nt * 8 + (l & 3) * 2 + (q & 1);
                        gq[row * 17 + col] = acc[mt][nt][q];
                    }
        }
        __syncthreads();

        {
            const int m = cm, jl = cjl;
            float gv[4];
            #pragma unroll
            for (int g = 0; g < 4; g++) {
                float x = xgp[g];
                int o = m * 17 + g * 4 + jl;
                #pragma unroll
                for (int q = 0; q < 8; q++) x += gs_[q * (64 * 17) + o];
                gv[g] = x;
            }
            float co = cs_[m * 4 + jl];
            float cn = sig_fast(gv[1]) * co + sig_fast(gv[0]) * tanh_fast(gv[3]);
            float hn = sig_fast(gv[2]) * cn;   // NOTE: no tanh on cell
            cs_[m * 4 + jl] = cn;
            __stcg(&hT_out[(jbase + jl) * B_ + m], hn);
        }

        if (s + 1 < S_) {
            __syncthreads();
            if (tid == 0) grid_bar_arrive_wait();
            __syncthreads();
        }
    }
}

// ---------------- final combine per batch ------------------------------------
__global__ __launch_bounds__(256) void final_kernel(
    const float* __restrict__ v, const float* __restrict__ W_dec,
    const float* __restrict__ b_dec, const float* __restrict__ W_gate,
    const float* __restrict__ b_gate, const float* __restrict__ b_dd,
    float* __restrict__ out)
{
    const int b = blockIdx.x;
    const int tid = threadIdx.x;

    float hd = 0.0f;
    for (int k = tid; k < H_; k += 256)
        hd += g_hT[0][k * B_ + b] * W_dec[k];

    float gs = 0.0f;
    const float* vb = &v[(size_t)b * S_ * F_];
    for (int idx = tid; idx < S_ * F_; idx += 256)
        gs += vb[idx] * W_gate[idx & (F_ - 1)];

    float ds = 0.0f;
    for (int s = tid; s < S_; s += 256)
        ds += g_ddp[b * S_ + s];

    __shared__ float red[3][256];
    red[0][tid] = hd; red[1][tid] = gs; red[2][tid] = ds;
    __syncthreads();
    for (int o = 128; o > 0; o >>= 1) {
        if (tid < o) {
            red[0][tid] += red[0][tid + o];
            red[1][tid] += red[1][tid + o];
            red[2][tid] += red[2][tid + o];
        }
        __syncthreads();
    }
    if (tid == 0) {
        float gt = sigmoidf_(red[1][0] * (1.0f / S_) + b_gate[0]);
        float op = sigmoidf_(red[0][0] + b_dec[0]);
        float dp = sigmoidf_(red[2][0] + b_dd[0]);
        out[b] = op * gt + dp * (1.0f - gt);
    }
}

// ---------------- launch ------------------------------------------------------
extern "C" void kernel_launch(void* const* d_in, const int* in_sizes, int n_in,
                              void* d_out, int out_size)
{
    const float* v       = (const float*)d_in[0];
    const int*   cat     = (const int*)d_in[1];
    const float* W_enc   = (const float*)d_in[2];
    const float* b_enc   = (const float*)d_in[3];
    const float* Wx      = (const float*)d_in[4];
    const float* bx      = (const float*)d_in[5];
    const float* Wh      = (const float*)d_in[6];
    const float* bh      = (const float*)d_in[7];
    const float* cat_emb = (const float*)d_in[8];
    const float* W_dec   = (const float*)d_in[9];
    const float* b_dec   = (const float*)d_in[10];
    const float* proto   = (const float*)d_in[11];
    const float* W_dd    = (const float*)d_in[12];
    const float* b_dd    = (const float*)d_in[13];
    const float* W_gate  = (const float*)d_in[14];
    const float* b_gate  = (const float*)d_in[15];
    float* out = (float*)d_out;

    const int gemm_smem = 2 * BUF_FLOATS * 4;                       // 48 KB
    const int lstm_smem = (8192 + 32768 + 8 * 64 * 17 + 256) * 4;   // ~196 KB
    cudaFuncSetAttribute(fuse_tc, cudaFuncAttributeMaxDynamicSharedMemorySize, gemm_smem);
    cudaFuncSetAttribute(xg_tc, cudaFuncAttributeMaxDynamicSharedMemorySize, gemm_smem);
    cudaFuncSetAttribute(lstm_persist, cudaFuncAttributeMaxDynamicSharedMemorySize,
                         lstm_smem);

    cat_normalize<<<1, 32>>>(cat);
    fuse_tc<<<FUSE_TILES + PROTO_BLK, 256, gemm_smem>>>(v, W_enc, b_enc, cat_emb,
                                                        proto, W_dd);
    xg_tc<<<XG_TILES + PROTO_BLK, 256, gemm_smem>>>(Wx, bx, bh, v, proto, W_dd);
    lstm_persist<<<128, 256, lstm_smem>>>(Wh);
    final_kernel<<<B_, 256>>>(v, W_dec, b_dec, W_gate, b_gate, b_dd, out);
}